// round 6
// baseline (speedup 1.0000x reference)
#include <cuda_runtime.h>

typedef unsigned long long u64;

// ---- packed f32x2 helpers (sm_103a) ----
__device__ __forceinline__ u64 pack2(float lo, float hi) {
    u64 d;
    asm("mov.b64 %0, {%1, %2};" : "=l"(d) : "r"(__float_as_uint(lo)), "r"(__float_as_uint(hi)));
    return d;
}
__device__ __forceinline__ void unpack2(u64 v, float& lo, float& hi) {
    unsigned a, b;
    asm("mov.b64 {%0, %1}, %2;" : "=r"(a), "=r"(b) : "l"(v));
    lo = __uint_as_float(a); hi = __uint_as_float(b);
}
__device__ __forceinline__ u64 fma2(u64 a, u64 b, u64 c) {
    u64 d;
    asm("fma.rn.f32x2 %0, %1, %2, %3;" : "=l"(d) : "l"(a), "l"(b), "l"(c));
    return d;
}
__device__ __forceinline__ u64 mul2(u64 a, u64 b) {
    u64 d;
    asm("mul.rn.f32x2 %0, %1, %2;" : "=l"(d) : "l"(a), "l"(b));
    return d;
}
__device__ __forceinline__ u64 add2(u64 a, u64 b) {
    u64 d;
    asm("add.rn.f32x2 %0, %1, %2;" : "=l"(d) : "l"(a), "l"(b));
    return d;
}
__device__ __forceinline__ u64 relu2(u64 v) {
    float lo, hi; unpack2(v, lo, hi);
    lo = fmaxf(lo, 0.0f); hi = fmaxf(hi, 0.0f);
    return pack2(lo, hi);
}
__device__ __forceinline__ u64 lds64(unsigned a) {
    u64 v;
    asm volatile("ld.shared.b64 %0, [%1];" : "=l"(v) : "r"(a));
    return v;
}
__device__ __forceinline__ void sts64(unsigned a, u64 v) {
    asm volatile("st.shared.b64 [%0], %1;" :: "r"(a), "l"(v));
}

// ---- problem constants ----
constexpr int W_DIM = 4096;
constexpr int C_DIM = 64;
constexpr int L_SEG = 512;            // outputs per warp
constexpr int SEGS  = W_DIM / L_SEG;  // 8
constexpr int BH    = 16 * 21;        // 336 rows
constexpr int PF    = 8;              // x LDG prefetch distance (steps)
constexpr int WU    = 64;             // warmup steps
constexpr int T_TOT = WU + L_SEG;     // 576 steps
constexpr int Y2_BYTES = 32 * 32 * 8; // y2 ring: 32 slots x 32 lanes x 8B = 8KB/warp
constexpr int SMEM_TOTAL = 4 * Y2_BYTES;  // 32KB per 128-thread block

// Cross-correlation, zero pad. pad_lo: d=1 -> 3, d=2 -> 7, d=4 -> 14.
// y1[w] = relu(sum_k x [w- 3+  k] * w1[k])
// y2[w] = relu(sum_k y1[w- 7+ 2k] * w2[k])   (y1 := 0 outside [0,W))
// y3[w] = relu(sum_k y2[w-14+ 4k] * w3[k])   (y2 := 0 outside [0,W))
//
// Pipelined schedule (t0 = s0-36), step i (u = i & 31):
//   LDG   x pos t0+i+PF -> xr[(u+PF)&15]           (register ring, 16 slots)
//   STAGE1 y1 @ t0+i-4  -> y1r[u&15]               (register ring, 16 slots)
//   STAGE2 y2 @ t0+i-12 -> smem ring slot u        (STS.64; ring size 32 = unroll)
//   STAGE3 y3 @ t0+i-28 -> store (main only)       (8x LDS.64, lags 2..30)
// y2 ring lives in smem: frees 64 regs -> 3 blocks/SM and scheduling slack.
// Same-lane STS->LDS needs no sync (per-thread smem ordering).

#define LOADX(u)                                                               \
    {                                                                          \
        u64 xv;                                                                \
        if (BOUNDARY) {                                                        \
            const int t = tld + (u);                                           \
            xv = (t >= 0 && t < W_DIM) ? *(const u64*)(lp + (u) * C_DIM) : 0ull; \
        } else {                                                               \
            xv = *(const u64*)(lp + (u) * C_DIM);                              \
        }                                                                      \
        xr[((u) + PF) & 15] = xv;                                              \
    }

#define STAGE1(u)                                                              \
    {                                                                          \
        u64 a0 = mul2(xr[((u) - 7) & 15], w1r[0]);                             \
        u64 a1 = mul2(xr[((u) - 6) & 15], w1r[1]);                             \
        a0 = fma2(xr[((u) - 5) & 15], w1r[2], a0);                             \
        a1 = fma2(xr[((u) - 4) & 15], w1r[3], a1);                             \
        a0 = fma2(xr[((u) - 3) & 15], w1r[4], a0);                             \
        a1 = fma2(xr[((u) - 2) & 15], w1r[5], a1);                             \
        a0 = fma2(xr[((u) - 1) & 15], w1r[6], a0);                             \
        a1 = fma2(xr[((u) - 0) & 15], w1r[7], a1);                             \
        u64 y1v = relu2(add2(a0, a1));                                         \
        if (BOUNDARY) {                                                        \
            const int p1 = tld + (u) - PF - 4;                                 \
            if (p1 < 0 || p1 >= W_DIM) y1v = 0ull;                             \
        }                                                                      \
        y1r[(u) & 15] = y1v;                                                   \
    }

#define STAGE2(u)                                                              \
    {                                                                          \
        u64 b0 = mul2(y1r[((u) - 15) & 15], w2r[0]);                           \
        u64 b1 = mul2(y1r[((u) - 13) & 15], w2r[1]);                           \
        b0 = fma2(y1r[((u) - 11) & 15], w2r[2], b0);                           \
        b1 = fma2(y1r[((u) -  9) & 15], w2r[3], b1);                           \
        b0 = fma2(y1r[((u) -  7) & 15], w2r[4], b0);                           \
        b1 = fma2(y1r[((u) -  5) & 15], w2r[5], b1);                           \
        b0 = fma2(y1r[((u) -  3) & 15], w2r[6], b0);                           \
        b1 = fma2(y1r[((u) -  1) & 15], w2r[7], b1);                           \
        u64 y2v = relu2(add2(b0, b1));                                         \
        if (BOUNDARY) {                                                        \
            const int p2 = tld + (u) - PF - 12;                                \
            if (p2 < 0 || p2 >= W_DIM) y2v = 0ull;                             \
        }                                                                      \
        sts64(swp + ((u) & 31) * 256, y2v);                                    \
    }

#define STAGE3_STORE(u)                                                        \
    {                                                                          \
        u64 c0 = mul2(lds64(swp + (((u) - 30) & 31) * 256), w3r[0]);           \
        u64 c1 = mul2(lds64(swp + (((u) - 26) & 31) * 256), w3r[1]);           \
        c0 = fma2(lds64(swp + (((u) - 22) & 31) * 256), w3r[2], c0);           \
        c1 = fma2(lds64(swp + (((u) - 18) & 31) * 256), w3r[3], c1);           \
        c0 = fma2(lds64(swp + (((u) - 14) & 31) * 256), w3r[4], c0);           \
        c1 = fma2(lds64(swp + (((u) - 10) & 31) * 256), w3r[5], c1);           \
        c0 = fma2(lds64(swp + (((u) -  6) & 31) * 256), w3r[6], c0);           \
        c1 = fma2(lds64(swp + (((u) -  2) & 31) * 256), w3r[7], c1);           \
        const u64 y3v = relu2(add2(c0, c1));                                   \
        __stcs((u64*)(sp + (u) * C_DIM), y3v);                                 \
    }

template<bool BOUNDARY>
__device__ __forceinline__ void run_seg(
    const float* __restrict__ x,
    const u64* w1r, const u64* w2r, const u64* w3r,
    float* __restrict__ out,
    int bh, int seg, int lane, unsigned swp)
{
    const int s0 = seg * L_SEG;
    const int t0 = s0 - 36;

    // running load pointer: position (t0 + ib + PF) at in-body offset u=0
    const float* lp = x + ((long long)bh * W_DIM + (t0 + PF)) * C_DIM + 2 * lane;
    float* sp = out + ((long long)bh * W_DIM + s0) * C_DIM + 2 * lane;
    int tld = t0 + PF;   // loaded position at offset u (boundary predicates)

    u64 xr[16], y1r[16];
    #pragma unroll
    for (int j = 0; j < 16; ++j) xr[j]  = 0ull;
    #pragma unroll
    for (int j = 0; j < 16; ++j) y1r[j] = 0ull;

    // preload positions t0..t0+PF-1 into slots 0..PF-1
    #pragma unroll
    for (int j = 0; j < PF; ++j) {
        if (BOUNDARY) {
            const int t = t0 + j;
            xr[j] = (t >= 0 && t < W_DIM)
                  ? *(const u64*)(lp + (j - PF) * C_DIM) : 0ull;
        } else {
            xr[j] = *(const u64*)(lp + (j - PF) * C_DIM);
        }
    }

    // warmup: stages 1-2 (fills y1 reg ring + y2 smem ring)
    for (int ib = 0; ib < WU; ib += 32) {
        #pragma unroll
        for (int u = 0; u < 32; ++u) {
            LOADX(u) STAGE1(u) STAGE2(u)
        }
        lp  += 32 * C_DIM;
        tld += 32;
    }

    // main: all stages, unconditional store
    for (int ib = WU; ib < T_TOT; ib += 32) {
        #pragma unroll
        for (int u = 0; u < 32; ++u) {
            LOADX(u) STAGE1(u) STAGE2(u) STAGE3_STORE(u)
        }
        lp  += 32 * C_DIM;
        sp  += 32 * C_DIM;
        tld += 32;
    }
}

__global__ void __launch_bounds__(128, 3)
conv_stack_kernel(const float* __restrict__ x,
                  const float* __restrict__ w1,
                  const float* __restrict__ w2,
                  const float* __restrict__ w3,
                  float* __restrict__ out)
{
    extern __shared__ char smem[];

    const int warp = blockIdx.x * 4 + (threadIdx.x >> 5);
    const int lane = threadIdx.x & 31;

    // per-warp y2 ring base + per-lane offset (8B per lane)
    const unsigned swp = (unsigned)__cvta_generic_to_shared(
        smem + (threadIdx.x >> 5) * Y2_BYTES) + lane * 8;

    const int bh  = warp >> 3;        // warp / SEGS
    const int seg = warp & 7;         // warp % SEGS

    u64 w1r[8], w2r[8], w3r[8];
    #pragma unroll
    for (int k = 0; k < 8; ++k) {
        w1r[k] = *(const u64*)(w1 + k * C_DIM + 2 * lane);
        w2r[k] = *(const u64*)(w2 + k * C_DIM + 2 * lane);
        w3r[k] = *(const u64*)(w3 + k * C_DIM + 2 * lane);
    }

    if (seg == 0 || seg == SEGS - 1) {
        run_seg<true >(x, w1r, w2r, w3r, out, bh, seg, lane, swp);
    } else {
        run_seg<false>(x, w1r, w2r, w3r, out, bh, seg, lane, swp);
    }
}

extern "C" void kernel_launch(void* const* d_in, const int* in_sizes, int n_in,
                              void* d_out, int out_size)
{
    const float* x  = (const float*)d_in[0];
    const float* w1 = (const float*)d_in[1];
    const float* w2 = (const float*)d_in[2];
    const float* w3 = (const float*)d_in[3];
    float* out = (float*)d_out;

    (void)in_sizes; (void)n_in; (void)out_size;

    cudaFuncSetAttribute(conv_stack_kernel,
                         cudaFuncAttributeMaxDynamicSharedMemorySize, SMEM_TOTAL);

    // 336 rows * 8 segs = 2688 warps -> 672 blocks of 128 threads
    conv_stack_kernel<<<(BH * SEGS) / 4, 128, SMEM_TOTAL>>>(x, w1, w2, w3, out);
}